// round 1
// baseline (speedup 1.0000x reference)
#include <cuda_runtime.h>
#include <mma.h>
#include <math.h>

using namespace nvcuda;

#define S_LEN 2048
#define DM    1024
#define NH    16
#define HD    64

// Scratch for Q, K, V projections (8 MB each). Static __device__ arrays per
// allocation-guard rules.
__device__ float g_q[S_LEN * DM];
__device__ float g_k[S_LEN * DM];
__device__ float g_v[S_LEN * DM];

// ---------------------------------------------------------------------------
// Kernel 1: QKV projection.  Y = X @ W  (M=2048, N=1024, K=1024), z selects W.
// BM=128, BN=64, BK=32. 256 threads = 8 warps (4 x 2), warp tile 32x32.
// ---------------------------------------------------------------------------
__global__ __launch_bounds__(256) void qkv_gemm_kernel(
    const float* __restrict__ X,
    const float* __restrict__ Wq,
    const float* __restrict__ Wk,
    const float* __restrict__ Wv)
{
    constexpr int BM = 128, BN = 64, BK = 32;
    const float* W = (blockIdx.z == 0) ? Wq : (blockIdx.z == 1) ? Wk : Wv;
    float*       Y = (blockIdx.z == 0) ? g_q : (blockIdx.z == 1) ? g_k : g_v;

    __shared__ float As[BM][BK + 4];
    __shared__ float Bs[BK][BN + 4];

    const int tid  = threadIdx.x;
    const int warp = tid >> 5;
    const int wm   = warp & 3;   // 0..3 -> 32-row strips
    const int wn   = warp >> 2;  // 0..1 -> 32-col strips

    const int row0 = blockIdx.y * BM;
    const int col0 = blockIdx.x * BN;

    wmma::fragment<wmma::accumulator, 16, 16, 8, float> acc[2][2];
    #pragma unroll
    for (int i = 0; i < 2; i++)
        #pragma unroll
        for (int j = 0; j < 2; j++)
            wmma::fill_fragment(acc[i][j], 0.0f);

    for (int k0 = 0; k0 < DM; k0 += BK) {
        // A tile: 128 x 32 floats = 1024 float4, 4 per thread
        #pragma unroll
        for (int it = 0; it < 4; it++) {
            int idx = tid + it * 256;
            int r = idx >> 3, c4 = idx & 7;
            float4 v4 = *(const float4*)&X[(size_t)(row0 + r) * DM + k0 + c4 * 4];
            *(float4*)&As[r][c4 * 4] = v4;
        }
        // B tile: 32 x 64 floats = 512 float4, 2 per thread
        #pragma unroll
        for (int it = 0; it < 2; it++) {
            int idx = tid + it * 256;
            int r = idx >> 4, c4 = idx & 15;
            float4 v4 = *(const float4*)&W[(size_t)(k0 + r) * DM + col0 + c4 * 4];
            *(float4*)&Bs[r][c4 * 4] = v4;
        }
        __syncthreads();

        #pragma unroll
        for (int kk = 0; kk < BK; kk += 8) {
            wmma::fragment<wmma::matrix_a, 16, 16, 8, wmma::precision::tf32,
                           wmma::row_major> a[2];
            wmma::fragment<wmma::matrix_b, 16, 16, 8, wmma::precision::tf32,
                           wmma::row_major> b[2];
            #pragma unroll
            for (int i = 0; i < 2; i++) {
                wmma::load_matrix_sync(a[i], &As[wm * 32 + i * 16][kk], BK + 4);
                #pragma unroll
                for (int e = 0; e < a[i].num_elements; e++)
                    a[i].x[e] = wmma::__float_to_tf32(a[i].x[e]);
            }
            #pragma unroll
            for (int j = 0; j < 2; j++) {
                wmma::load_matrix_sync(b[j], &Bs[kk][wn * 32 + j * 16], BN + 4);
                #pragma unroll
                for (int e = 0; e < b[j].num_elements; e++)
                    b[j].x[e] = wmma::__float_to_tf32(b[j].x[e]);
            }
            #pragma unroll
            for (int i = 0; i < 2; i++)
                #pragma unroll
                for (int j = 0; j < 2; j++)
                    wmma::mma_sync(acc[i][j], a[i], b[j], acc[i][j]);
        }
        __syncthreads();
    }

    #pragma unroll
    for (int i = 0; i < 2; i++)
        #pragma unroll
        for (int j = 0; j < 2; j++)
            wmma::store_matrix_sync(
                &Y[(size_t)(row0 + wm * 32 + i * 16) * DM + col0 + wn * 32 + j * 16],
                acc[i][j], DM, wmma::mem_row_major);
}

// ---------------------------------------------------------------------------
// Kernel 2: scores[h][q][k] = (q_h . k_h) / 8, written into probs region.
// Per block: 64x64 output tile, full K=64 in smem. 128 threads = 4 warps (2x2).
// ---------------------------------------------------------------------------
__global__ __launch_bounds__(128) void scores_kernel(float* __restrict__ probs)
{
    const int h = blockIdx.z;
    __shared__ float Qs[64][68];
    __shared__ float Ks[64][68];

    const int tid  = threadIdx.x;
    const int warp = tid >> 5;
    const int wm   = warp & 1;
    const int wn   = warp >> 1;

    const int qrow0 = blockIdx.y * 64;
    const int krow0 = blockIdx.x * 64;
    const float* qp = g_q + h * HD;
    const float* kp = g_k + h * HD;

    // 64 rows x 16 float4 each for Q and K
    for (int idx = tid; idx < 64 * 16; idx += 128) {
        int r = idx >> 4, c4 = idx & 15;
        *(float4*)&Qs[r][c4 * 4] =
            *(const float4*)&qp[(size_t)(qrow0 + r) * DM + c4 * 4];
        *(float4*)&Ks[r][c4 * 4] =
            *(const float4*)&kp[(size_t)(krow0 + r) * DM + c4 * 4];
    }
    __syncthreads();

    wmma::fragment<wmma::accumulator, 16, 16, 8, float> acc[2][2];
    #pragma unroll
    for (int i = 0; i < 2; i++)
        #pragma unroll
        for (int j = 0; j < 2; j++)
            wmma::fill_fragment(acc[i][j], 0.0f);

    #pragma unroll
    for (int kk = 0; kk < 64; kk += 8) {
        wmma::fragment<wmma::matrix_a, 16, 16, 8, wmma::precision::tf32,
                       wmma::row_major> a[2];
        wmma::fragment<wmma::matrix_b, 16, 16, 8, wmma::precision::tf32,
                       wmma::col_major> b[2];
        #pragma unroll
        for (int i = 0; i < 2; i++) {
            wmma::load_matrix_sync(a[i], &Qs[wm * 32 + i * 16][kk], 68);
            #pragma unroll
            for (int e = 0; e < a[i].num_elements; e++)
                a[i].x[e] = wmma::__float_to_tf32(a[i].x[e]);
        }
        #pragma unroll
        for (int j = 0; j < 2; j++) {
            // col_major: element (k,n) at base[n*ld + k]; base = &Ks[n0][kk]
            wmma::load_matrix_sync(b[j], &Ks[wn * 32 + j * 16][kk], 68);
            #pragma unroll
            for (int e = 0; e < b[j].num_elements; e++)
                b[j].x[e] = wmma::__float_to_tf32(b[j].x[e]);
        }
        #pragma unroll
        for (int i = 0; i < 2; i++)
            #pragma unroll
            for (int j = 0; j < 2; j++)
                wmma::mma_sync(acc[i][j], a[i], b[j], acc[i][j]);
    }

    float* outp = probs + (size_t)h * S_LEN * S_LEN;
    #pragma unroll
    for (int i = 0; i < 2; i++)
        #pragma unroll
        for (int j = 0; j < 2; j++) {
            #pragma unroll
            for (int e = 0; e < acc[i][j].num_elements; e++)
                acc[i][j].x[e] *= 0.125f;   // 1/sqrt(64)
            wmma::store_matrix_sync(
                &outp[(size_t)(qrow0 + wm * 32 + i * 16) * S_LEN +
                      krow0 + wn * 32 + j * 16],
                acc[i][j], S_LEN, wmma::mem_row_major);
        }
}

// ---------------------------------------------------------------------------
// Kernel 3: row softmax in place over probs rows of length 2048.
// One block (256 threads) per row; 8 elements per thread.
// ---------------------------------------------------------------------------
__global__ __launch_bounds__(256) void softmax_kernel(float* __restrict__ probs)
{
    float* row = probs + (size_t)blockIdx.x * S_LEN;
    const int tid  = threadIdx.x;
    const int lane = tid & 31;
    const int warp = tid >> 5;
    __shared__ float red[8];

    float v[8];
    float m = -INFINITY;
    #pragma unroll
    for (int i = 0; i < 8; i++) {
        v[i] = row[tid + i * 256];
        m = fmaxf(m, v[i]);
    }
    #pragma unroll
    for (int o = 16; o > 0; o >>= 1)
        m = fmaxf(m, __shfl_xor_sync(0xFFFFFFFFu, m, o));
    if (lane == 0) red[warp] = m;
    __syncthreads();
    m = red[0];
    #pragma unroll
    for (int w = 1; w < 8; w++) m = fmaxf(m, red[w]);

    float s = 0.0f;
    #pragma unroll
    for (int i = 0; i < 8; i++) {
        v[i] = expf(v[i] - m);
        s += v[i];
    }
    #pragma unroll
    for (int o = 16; o > 0; o >>= 1)
        s += __shfl_xor_sync(0xFFFFFFFFu, s, o);
    __syncthreads();
    if (lane == 0) red[warp] = s;
    __syncthreads();
    s = 0.0f;
    #pragma unroll
    for (int w = 0; w < 8; w++) s += red[w];

    const float inv = 1.0f / s;
    #pragma unroll
    for (int i = 0; i < 8; i++)
        row[tid + i * 256] = v[i] * inv;
}

// ---------------------------------------------------------------------------
// Kernel 4: context[q][h*64+d] = sum_k probs[h][q][k] * v[k][h*64+d].
// Per head: M=2048, N=64, K=2048. BM=128, BN=64, BK=32; 8 warps (4x2).
// ---------------------------------------------------------------------------
__global__ __launch_bounds__(256) void pv_kernel(
    const float* __restrict__ probs, float* __restrict__ ctx)
{
    constexpr int BM = 128, BK = 32;
    const int h = blockIdx.z;
    const float* P  = probs + (size_t)h * S_LEN * S_LEN;
    const float* vp = g_v + h * HD;

    __shared__ float Ps[BM][BK + 4];
    __shared__ float Vs[BK][64 + 4];

    const int tid  = threadIdx.x;
    const int warp = tid >> 5;
    const int wm   = warp & 3;
    const int wn   = warp >> 2;
    const int row0 = blockIdx.y * BM;

    wmma::fragment<wmma::accumulator, 16, 16, 8, float> acc[2][2];
    #pragma unroll
    for (int i = 0; i < 2; i++)
        #pragma unroll
        for (int j = 0; j < 2; j++)
            wmma::fill_fragment(acc[i][j], 0.0f);

    for (int k0 = 0; k0 < S_LEN; k0 += BK) {
        #pragma unroll
        for (int it = 0; it < 4; it++) {
            int idx = tid + it * 256;
            int r = idx >> 3, c4 = idx & 7;
            float4 v4 = *(const float4*)&P[(size_t)(row0 + r) * S_LEN + k0 + c4 * 4];
            *(float4*)&Ps[r][c4 * 4] = v4;
        }
        #pragma unroll
        for (int it = 0; it < 2; it++) {
            int idx = tid + it * 256;
            int r = idx >> 4, c4 = idx & 15;
            float4 v4 = *(const float4*)&vp[(size_t)(k0 + r) * DM + c4 * 4];
            *(float4*)&Vs[r][c4 * 4] = v4;
        }
        __syncthreads();

        #pragma unroll
        for (int kk = 0; kk < BK; kk += 8) {
            wmma::fragment<wmma::matrix_a, 16, 16, 8, wmma::precision::tf32,
                           wmma::row_major> a[2];
            wmma::fragment<wmma::matrix_b, 16, 16, 8, wmma::precision::tf32,
                           wmma::row_major> b[2];
            #pragma unroll
            for (int i = 0; i < 2; i++) {
                wmma::load_matrix_sync(a[i], &Ps[wm * 32 + i * 16][kk], BK + 4);
                #pragma unroll
                for (int e = 0; e < a[i].num_elements; e++)
                    a[i].x[e] = wmma::__float_to_tf32(a[i].x[e]);
            }
            #pragma unroll
            for (int j = 0; j < 2; j++) {
                wmma::load_matrix_sync(b[j], &Vs[kk][wn * 32 + j * 16], 68);
                #pragma unroll
                for (int e = 0; e < b[j].num_elements; e++)
                    b[j].x[e] = wmma::__float_to_tf32(b[j].x[e]);
            }
            #pragma unroll
            for (int i = 0; i < 2; i++)
                #pragma unroll
                for (int j = 0; j < 2; j++)
                    wmma::mma_sync(acc[i][j], a[i], b[j], acc[i][j]);
        }
        __syncthreads();
    }

    #pragma unroll
    for (int i = 0; i < 2; i++)
        #pragma unroll
        for (int j = 0; j < 2; j++)
            wmma::store_matrix_sync(
                &ctx[(size_t)(row0 + wm * 32 + i * 16) * DM + h * HD +
                     wn * 32 + j * 16],
                acc[i][j], DM, wmma::mem_row_major);
}

// ---------------------------------------------------------------------------
// Launch. d_out layout: context (2048*1024 floats) then probs (16*2048*2048).
// ---------------------------------------------------------------------------
extern "C" void kernel_launch(void* const* d_in, const int* in_sizes, int n_in,
                              void* d_out, int out_size)
{
    const float* hs = (const float*)d_in[0];
    const float* Wq = (const float*)d_in[1];
    const float* Wk = (const float*)d_in[2];
    const float* Wv = (const float*)d_in[3];

    float* ctx   = (float*)d_out;
    float* probs = ctx + (size_t)S_LEN * DM;

    qkv_gemm_kernel<<<dim3(DM / 64, S_LEN / 128, 3), 256>>>(hs, Wq, Wk, Wv);
    scores_kernel<<<dim3(S_LEN / 64, S_LEN / 64, NH), 128>>>(probs);
    softmax_kernel<<<dim3(NH * S_LEN), 256>>>(probs);
    pv_kernel<<<dim3(1, S_LEN / 128, NH), 256>>>(probs, ctx);
}